// round 1
// baseline (speedup 1.0000x reference)
#include <cuda_runtime.h>
#include <cstdint>

#define T_LEN 16384
#define HID   256
#define EMB   16
#define TMP   128
#define EVD   2048
#define NCTA  8
#define NEG_SLOPE 0.01f

// Scratch (static device globals — no allocation at runtime)
__device__ float g_X[T_LEN * TMP];   // 8 MB: bilstm part of layer-1 preactivation (incl. b1)
__device__ float g_C[EVD * TMP];     // 1 MB: event-embedding part of layer-1 preactivation
__device__ int   g_idx[T_LEN];       // argmax index emitted at each step

// ---------------------------------------------------------------------------
// Phase 1a: X[t][j] = dot(bilstm[t, 0:256], W1[j, 0:256]) + b1[j]
// ---------------------------------------------------------------------------
__global__ void __launch_bounds__(128) x_kernel(const float* __restrict__ bilstm,
                                                const float* __restrict__ W1,
                                                const float* __restrict__ b1) {
    __shared__ __align__(16) float row[HID];
    const int t = blockIdx.x;
    const int j = threadIdx.x;
    row[j]       = bilstm[t * HID + j];
    row[j + 128] = bilstm[t * HID + 128 + j];
    __syncthreads();

    const float4* w4 = reinterpret_cast<const float4*>(W1 + j * (HID + EMB));
    const float4* r4 = reinterpret_cast<const float4*>(row);
    float a0 = 0.f, a1 = 0.f, a2 = 0.f, a3 = 0.f;
#pragma unroll
    for (int k = 0; k < HID / 4; k++) {
        float4 w = w4[k];
        float4 h = r4[k];
        a0 += w.x * h.x; a1 += w.y * h.y; a2 += w.z * h.z; a3 += w.w * h.w;
    }
    g_X[t * TMP + j] = (a0 + a1) + (a2 + a3) + b1[j];
}

// ---------------------------------------------------------------------------
// Phase 1b: C[e][j] = dot(emb_table[e, :], W1[j, 256:272])
// ---------------------------------------------------------------------------
__global__ void __launch_bounds__(128) c_kernel(const float* __restrict__ emb,
                                                const float* __restrict__ W1) {
    __shared__ __align__(16) float e[EMB];
    const int ei = blockIdx.x;
    const int j  = threadIdx.x;
    if (j < EMB) e[j] = emb[ei * EMB + j];
    __syncthreads();

    const float4* w4 = reinterpret_cast<const float4*>(W1 + j * (HID + EMB) + HID);
    const float4* e4 = reinterpret_cast<const float4*>(e);
    float a = 0.f;
#pragma unroll
    for (int k = 0; k < EMB / 4; k++) {
        float4 w = w4[k];
        float4 h = e4[k];
        a += w.x * h.x + w.y * h.y + w.z * h.z + w.w * h.w;
    }
    g_C[ei * TMP + j] = a;
}

// ---------------------------------------------------------------------------
// Phase 2: sequential greedy decode. Cluster of 8 CTAs x 256 threads.
// Each thread owns one logit row (W2 row in registers). Per step:
//   h = leaky(X[t] + C[idx]) in SMEM -> per-thread GEMV -> cluster argmax.
// ---------------------------------------------------------------------------
__global__ void __cluster_dims__(NCTA, 1, 1) __launch_bounds__(256, 1)
seq_kernel(const float* __restrict__ W2, const float* __restrict__ b2,
           const int* __restrict__ initp) {
    __shared__ __align__(16) float sh_h[TMP];
    __shared__ unsigned long long sh_warp[8];
    __shared__ unsigned long long sh_cand[2][NCTA];  // double-buffered cluster candidates (rank0's used)
    __shared__ int sh_bcast;

    unsigned rank;
    asm("mov.u32 %0, %%cluster_ctarank;" : "=r"(rank));
    const int tid  = threadIdx.x;
    const int lane = tid & 31;
    const int wid  = tid >> 5;
    const int r    = (int)rank * 256 + tid;   // this thread's logit row

    // Pin W2 row + bias in registers.
    const float4* w4 = reinterpret_cast<const float4*>(W2 + r * TMP);
    float4 w[TMP / 4];
#pragma unroll
    for (int k = 0; k < TMP / 4; k++) w[k] = w4[k];
    const float bias = b2[r];

    int idx = *initp;
    float xv = (tid < TMP) ? g_X[tid] : 0.f;

    for (int t = 0; t < T_LEN; t++) {
        // h = leaky(X[t] + C[idx])
        if (tid < TMP) {
            float v = xv + g_C[idx * TMP + tid];
            sh_h[tid] = (v > 0.f) ? v : NEG_SLOPE * v;
        }
        // prefetch next X row (independent of idx)
        float xn = 0.f;
        if (tid < TMP && t + 1 < T_LEN) xn = g_X[(t + 1) * TMP + tid];
        __syncthreads();

        // GEMV: logit = W2[r] . h + b2[r]
        float a0 = bias, a1 = 0.f, a2 = 0.f, a3 = 0.f;
        const float4* h4 = reinterpret_cast<const float4*>(sh_h);
#pragma unroll
        for (int k = 0; k < TMP / 4; k++) {
            float4 hh = h4[k];
            a0 += w[k].x * hh.x; a1 += w[k].y * hh.y;
            a2 += w[k].z * hh.z; a3 += w[k].w * hh.w;
        }
        const float acc = (a0 + a1) + (a2 + a3);

        // warp argmax: monotone float->uint key; tie -> lowest lane (= lowest row)
        unsigned key = __float_as_uint(acc);
        key ^= (key & 0x80000000u) ? 0xFFFFFFFFu : 0x80000000u;
        const unsigned wmax = __reduce_max_sync(0xFFFFFFFFu, key);
        const unsigned ball = __ballot_sync(0xFFFFFFFFu, key == wmax);
        const int wl = __ffs(ball) - 1;
        if (lane == 0) {
            const int rwin = (int)rank * 256 + wid * 32 + wl;
            sh_warp[wid] = ((unsigned long long)wmax << 32) | (unsigned)(2047 - rwin);
        }
        __syncthreads();

        // CTA stage + push candidate to rank 0 (key encodes global row => ties resolve globally)
        if (tid == 0) {
            unsigned long long best = sh_warp[0];
#pragma unroll
            for (int i = 1; i < 8; i++) {
                const unsigned long long v = sh_warp[i];
                best = (v > best) ? v : best;
            }
            const unsigned laddr = (unsigned)__cvta_generic_to_shared(&sh_cand[t & 1][rank]);
            unsigned raddr;
            asm("mapa.shared::cluster.u32 %0, %1, %2;" : "=r"(raddr) : "r"(laddr), "r"(0));
            asm volatile("st.shared::cluster.u64 [%0], %1;" :: "r"(raddr), "l"(best) : "memory");
        }
        asm volatile("barrier.cluster.arrive.aligned;" ::: "memory");
        asm volatile("barrier.cluster.wait.aligned;" ::: "memory");

        // every CTA reads the 8 candidates from rank 0 and reduces
        if (tid == 0) {
            const unsigned laddr = (unsigned)__cvta_generic_to_shared(&sh_cand[t & 1][0]);
            unsigned raddr;
            asm("mapa.shared::cluster.u32 %0, %1, %2;" : "=r"(raddr) : "r"(laddr), "r"(0));
            unsigned long long best = 0ULL;
#pragma unroll
            for (int i = 0; i < NCTA; i++) {
                unsigned long long v;
                asm volatile("ld.shared::cluster.u64 %0, [%1];" : "=l"(v) : "r"(raddr + i * 8) : "memory");
                best = (v > best) ? v : best;
            }
            const int win = 2047 - (int)(best & 0xFFFFFFFFULL);
            sh_bcast = win;
            if (rank == 0) g_idx[t] = win;
        }
        __syncthreads();
        idx = sh_bcast;
        xv  = xn;
    }
}

// ---------------------------------------------------------------------------
// Phase 3: recompute logits for all t (4 rows per CTA), log_softmax, write
// all three outputs: [T*2048 log_probs | T*16 emb | T index-as-float].
// ---------------------------------------------------------------------------
__global__ void __launch_bounds__(256) out_kernel(const float* __restrict__ W2,
                                                  const float* __restrict__ b2,
                                                  const float* __restrict__ emb,
                                                  const int* __restrict__ initp,
                                                  float* __restrict__ out) {
    __shared__ __align__(16) float sh_h[4][TMP];
    __shared__ float red[8];
    const int t0  = blockIdx.x * 4;
    const int tid = threadIdx.x;
    const int lane = tid & 31;
    const int wid  = tid >> 5;

    // rebuild h rows exactly as in seq_kernel
    for (int q = tid; q < 4 * TMP; q += 256) {
        const int rr = q >> 7, j = q & 127;
        const int t = t0 + rr;
        const int in_idx = (t == 0) ? *initp : g_idx[t - 1];
        float v = g_X[t * TMP + j] + g_C[in_idx * TMP + j];
        sh_h[rr][j] = (v > 0.f) ? v : NEG_SLOPE * v;
    }
    __syncthreads();

    float acc[4][8];
#pragma unroll
    for (int rr = 0; rr < 4; rr++)
#pragma unroll
        for (int cj = 0; cj < 8; cj++) acc[rr][cj] = 0.f;

    const float4* W24 = reinterpret_cast<const float4*>(W2);
#pragma unroll 4
    for (int k = 0; k < TMP / 4; k++) {
        float4 hh[4];
#pragma unroll
        for (int rr = 0; rr < 4; rr++)
            hh[rr] = reinterpret_cast<const float4*>(sh_h[rr])[k];
#pragma unroll
        for (int cj = 0; cj < 8; cj++) {
            const int c = tid + 256 * cj;
            const float4 w = W24[c * (TMP / 4) + k];
#pragma unroll
            for (int rr = 0; rr < 4; rr++)
                acc[rr][cj] += w.x * hh[rr].x + w.y * hh[rr].y +
                               w.z * hh[rr].z + w.w * hh[rr].w;
        }
    }
#pragma unroll
    for (int cj = 0; cj < 8; cj++) {
        const float b = b2[tid + 256 * cj];
#pragma unroll
        for (int rr = 0; rr < 4; rr++) acc[rr][cj] += b;
    }

    // log_softmax per row, then write
    for (int rr = 0; rr < 4; rr++) {
        float m = acc[rr][0];
#pragma unroll
        for (int cj = 1; cj < 8; cj++) m = fmaxf(m, acc[rr][cj]);
#pragma unroll
        for (int o = 16; o > 0; o >>= 1) m = fmaxf(m, __shfl_xor_sync(0xFFFFFFFFu, m, o));
        if (lane == 0) red[wid] = m;
        __syncthreads();
        float M = red[0];
#pragma unroll
        for (int i = 1; i < 8; i++) M = fmaxf(M, red[i]);
        __syncthreads();

        float s = 0.f;
#pragma unroll
        for (int cj = 0; cj < 8; cj++) s += __expf(acc[rr][cj] - M);
#pragma unroll
        for (int o = 16; o > 0; o >>= 1) s += __shfl_xor_sync(0xFFFFFFFFu, s, o);
        if (lane == 0) red[wid] = s;
        __syncthreads();
        float S = 0.f;
#pragma unroll
        for (int i = 0; i < 8; i++) S += red[i];
        __syncthreads();

        const float lse = M + __logf(S);
        const int t = t0 + rr;
#pragma unroll
        for (int cj = 0; cj < 8; cj++)
            out[(size_t)t * EVD + tid + 256 * cj] = acc[rr][cj] - lse;
    }

    // ner_emb and ner_index outputs
    float* out_emb = out + (size_t)T_LEN * EVD;
    float* out_idx = out_emb + (size_t)T_LEN * EMB;
    if (tid < 4 * EMB) {
        const int rr = tid >> 4, j = tid & 15;
        const int t = t0 + rr;
        out_emb[t * EMB + j] = emb[g_idx[t] * EMB + j];
    }
    if (tid < 4) {
        const int t = t0 + tid;
        out_idx[t] = (float)g_idx[t];
    }
}

// ---------------------------------------------------------------------------
extern "C" void kernel_launch(void* const* d_in, const int* in_sizes, int n_in,
                              void* d_out, int out_size) {
    const float* bilstm = (const float*)d_in[0];
    const float* emb    = (const float*)d_in[1];
    const float* W1     = (const float*)d_in[2];
    const float* b1     = (const float*)d_in[3];
    const float* W2     = (const float*)d_in[4];
    const float* b2     = (const float*)d_in[5];
    const int*   init   = (const int*)d_in[6];
    float* out = (float*)d_out;

    x_kernel<<<T_LEN, 128>>>(bilstm, W1, b1);
    c_kernel<<<EVD, 128>>>(emb, W1);
    seq_kernel<<<NCTA, 256>>>(W2, b2, init);
    out_kernel<<<T_LEN / 4, 256>>>(W2, b2, emb, init, out);
}